// round 6
// baseline (speedup 1.0000x reference)
#include <cuda_runtime.h>
#include <cuda_fp16.h>
#include <math.h>
#include <stdint.h>

#define Bb 16
#define Nn 8192
#define Dd 384
#define KN 16
#define KD 8
#define Hh 128
#define STEPS 3
#define M_TOT (Bb*Nn)   // 131072
#define NB 256          // fused output width (coin 0..127 | path 128..255)

// GEMM tiling: CTA 64 rows x 256 cols, K-chunk 32, 12 chunks
#define APADH 40        // halves per A smem row (80B stride, odd multiple of 16B)
#define BPADH 264       // halves per B smem row (528B stride, odd multiple of 16B)
// per-buffer: A [0, 5120), B [5120, 22016)
#define SMBUF 22016
#define SM_TOTAL 44032
// epilogue aliases (within 44KB): ep[64][132] @0 (33792B)
#define EP_W2 33792
#define EP_QH 37888
#define EP_B2 38400

// ---- scratch (alloc-free: __device__ globals, fully rewritten every launch) ----
__device__ float g_Cp[(size_t)M_TOT*Hh];      // path hidden pre-act (sent part)   64MB
__device__ float g_amps[M_TOT*KD];            // coin amplitudes                    4MB
__device__ float g_t[2][M_TOT*KD];            // walk gather arrays               2x4MB
__device__ float g_nsL[M_TOT*KD];             // last step raw ns                   4MB
__device__ float g_qh[2*Bb*Hh];               // per-batch q@W + bias (coin, path)
__device__ float g_part[Bb*64];               // per-block sumsq partials
__device__ __half g_Bh[Dd*NB];                // fused W1, fp16, [kchunk16][k16][n]

// ================= helpers =================
__device__ __forceinline__ uint32_t smem_u32(const void* p) {
    uint32_t a;
    asm("{ .reg .u64 t; cvta.to.shared.u64 t, %1; cvt.u32.u64 %0, t; }" : "=r"(a) : "l"(p));
    return a;
}
__device__ __forceinline__ void ldsm4(unsigned &r0, unsigned &r1, unsigned &r2, unsigned &r3,
                                      unsigned addr) {
    asm volatile("ldmatrix.sync.aligned.m8n8.x4.shared.b16 {%0,%1,%2,%3}, [%4];"
                 : "=r"(r0), "=r"(r1), "=r"(r2), "=r"(r3) : "r"(addr));
}
__device__ __forceinline__ void ldsm4t(unsigned &r0, unsigned &r1, unsigned &r2, unsigned &r3,
                                       unsigned addr) {
    asm volatile("ldmatrix.sync.aligned.m8n8.x4.trans.shared.b16 {%0,%1,%2,%3}, [%4];"
                 : "=r"(r0), "=r"(r1), "=r"(r2), "=r"(r3) : "r"(addr));
}
__device__ __forceinline__ void mma16816(float* c, const unsigned* a, unsigned b0, unsigned b1) {
    asm volatile(
        "mma.sync.aligned.m16n8k16.row.col.f32.f16.f16.f32 "
        "{%0,%1,%2,%3}, {%4,%5,%6,%7}, {%8,%9}, {%0,%1,%2,%3};"
        : "+f"(c[0]), "+f"(c[1]), "+f"(c[2]), "+f"(c[3])
        : "r"(a[0]), "r"(a[1]), "r"(a[2]), "r"(a[3]), "r"(b0), "r"(b1));
}
__device__ __forceinline__ uint32_t pack_h2(__half a, __half b) {
    __half2 t; t.x = a; t.y = b;
    return *(uint32_t*)&t;
}

// ---------------------------------------------------------------------------
// per-batch q contribution, parallel over k-chunks: 512 threads = 128 h x 4 kc
// ---------------------------------------------------------------------------
__global__ void qh_kernel(const float* __restrict__ q,
                          const float* __restrict__ cw1, const float* __restrict__ cb1,
                          const float* __restrict__ pw1, const float* __restrict__ pb1) {
    __shared__ float red[4][Hh];
    int b = blockIdx.x, which = blockIdx.y;
    int h = threadIdx.x & 127, kc = threadIdx.x >> 7;
    const float* w1   = which ? pw1 : cw1;
    const float* bias = which ? pb1 : cb1;
    int rowoff = which ? (Dd + KD) : Dd;
    const float* qb = q + b*Dd;
    float acc = 0.f;
    #pragma unroll 4
    for (int k = kc*96; k < kc*96 + 96; k++)
        acc = fmaf(qb[k], w1[(size_t)(rowoff + k)*Hh + h], acc);
    red[kc][h] = acc;
    __syncthreads();
    if (kc == 0)
        g_qh[(which*Bb + b)*Hh + h] = bias[h] + ((red[0][h] + red[1][h])
                                              +  (red[2][h] + red[3][h]));
}

// ---------------------------------------------------------------------------
// pre-convert fused W1 sent-block to fp16, layout [k/16][k%16][n] (n<128 coin)
// ---------------------------------------------------------------------------
__global__ void prepB_kernel(const float* __restrict__ cw1, const float* __restrict__ pw1) {
    int k = blockIdx.x;          // 0..383
    int n = threadIdx.x;         // 0..255
    const float* w = (n < Hh) ? cw1 : pw1;
    float v = w[(size_t)k*Hh + (n & (Hh-1))];
    g_Bh[(k >> 4)*(16*NB) + (k & 15)*NB + n] = __float2half_rn(v);
}

// ---------------------------------------------------------------------------
// HMMA GEMM: CTA 64 rows x 256 cols, K=384 in 12 chunks of 32, fp16 single
// pass, fp32 accum, double-buffered smem, 2 CTAs/SM for latency overlap.
// 8 warps = 2(M) x 4(N), warp tile 32x64.
// Fused epilogue: cols 0..127 -> coin layer-2 -> g_amps & g_t[0];
//                 cols 128..255 -> g_Cp.
// ---------------------------------------------------------------------------
__global__ void __launch_bounds__(256, 2)
gemm_hmma(const float* __restrict__ A,
          const float* __restrict__ cw2, const float* __restrict__ cb2) {
    extern __shared__ char smem[];
    const uint32_t sbase = smem_u32(smem);
    const int tid = threadIdx.x, lane = tid & 31, wid = tid >> 5;
    const int wm = wid >> 2, wn = wid & 3;
    const size_t row0 = (size_t)blockIdx.x * 64;

    float c[2][8][4];
    #pragma unroll
    for (int i = 0; i < 2; i++)
        #pragma unroll
        for (int j = 0; j < 8; j++)
            #pragma unroll
            for (int l = 0; l < 4; l++) c[i][j][l] = 0.f;

    // A load: thread -> (row = tid>>2, 8 floats at col8 = (tid&3)*8)
    const int arow = tid >> 2, acol8 = (tid & 3)*8;
    const float* Ap = A + (row0 + arow)*Dd + acol8;
    const uint32_t a_sts = (uint32_t)arow*80 + (uint32_t)acol8*2;
    // B load: thread -> (krow = tid>>3, 32 halves at n32 = (tid&7)*32)
    const int bkrow = tid >> 3, bn32 = (tid & 7)*32;
    const uint32_t b_sts = 5120u + (uint32_t)bkrow*528 + (uint32_t)bn32*2;
    const int b_src0 = (bkrow >> 4)*4096 + (bkrow & 15)*NB + bn32;

    // ldmatrix lane offsets
    const uint32_t a_lane = (uint32_t)(wm*32 + (lane & 15))*80 + (uint32_t)(lane >> 4)*16;
    const uint32_t b_lane = 5120u + (uint32_t)((lane & 7) + ((lane >> 3) & 1)*8)*528
                          + (uint32_t)(wn*64 + (lane >> 4)*8)*2;

    float4 sA[2]; uint4 sB[4];

    #define LDG_CHUNK(ch) do {                                                 \
        sA[0] = *(const float4*)(Ap + (ch)*32);                                \
        sA[1] = *(const float4*)(Ap + (ch)*32 + 4);                            \
        _Pragma("unroll")                                                      \
        for (int _j = 0; _j < 4; _j++)                                         \
            sB[_j] = *(const uint4*)(g_Bh + (ch)*8192 + b_src0 + _j*8);        \
    } while (0)

    #define STS_CHUNK(bufbyte) do {                                           \
        char* _bc = smem + (bufbyte);                                          \
        float _v[8] = {sA[0].x, sA[0].y, sA[0].z, sA[0].w,                     \
                       sA[1].x, sA[1].y, sA[1].z, sA[1].w};                    \
        uint32_t _p[4];                                                        \
        _Pragma("unroll")                                                      \
        for (int _i = 0; _i < 4; _i++)                                         \
            _p[_i] = pack_h2(__float2half_rn(_v[2*_i]),                        \
                             __float2half_rn(_v[2*_i+1]));                     \
        *(uint4*)(_bc + a_sts) = make_uint4(_p[0], _p[1], _p[2], _p[3]);       \
        _Pragma("unroll")                                                      \
        for (int _j = 0; _j < 4; _j++)                                         \
            *(uint4*)(_bc + b_sts + _j*16) = sB[_j];                           \
    } while (0)

    LDG_CHUNK(0);
    STS_CHUNK(0);
    LDG_CHUNK(1);
    __syncthreads();

    for (int ch = 0; ch < 12; ch++) {
        const uint32_t sb0 = sbase + (uint32_t)(ch & 1)*SMBUF;
        #pragma unroll
        for (int k16 = 0; k16 < 2; k16++) {
            unsigned af[2][4];
            #pragma unroll
            for (int rg = 0; rg < 2; rg++)
                ldsm4(af[rg][0], af[rg][1], af[rg][2], af[rg][3],
                      sb0 + a_lane + (uint32_t)rg*(16*80) + (uint32_t)k16*32);
            #pragma unroll
            for (int pr = 0; pr < 4; pr++) {
                unsigned b0, b1, b2_, b3;
                ldsm4t(b0, b1, b2_, b3,
                       sb0 + b_lane + (uint32_t)k16*(16*528) + (uint32_t)pr*32);
                #pragma unroll
                for (int rg = 0; rg < 2; rg++) {
                    mma16816(c[rg][2*pr],     af[rg], b0,  b1);
                    mma16816(c[rg][2*pr + 1], af[rg], b2_, b3);
                }
            }
        }
        if (ch < 11) STS_CHUNK((uint32_t)((ch + 1) & 1)*SMBUF);
        if (ch + 2 < 12) LDG_CHUNK(ch + 2);
        __syncthreads();
    }

    // ---- epilogue ----
    const int b = blockIdx.x >> 7;             // 128 tiles per batch
    float* ep   = (float*)smem;                // [64][132]
    float* w2s  = (float*)(smem + EP_W2);
    float* qhs  = (float*)(smem + EP_QH);
    float* b2s  = (float*)(smem + EP_B2);
    for (int i = tid; i < Hh*KD; i += 256) w2s[i] = cw2[i];
    if (tid < Hh) qhs[tid] = g_qh[b*Hh + tid];
    if (tid < KD) b2s[tid] = cb2[tid];
    __syncthreads();

    const int gr = lane >> 2, gc2 = (lane & 3)*2;
    if (wn < 2) {
        // coin half: stage relu(c + qh) into ep
        #pragma unroll
        for (int rg = 0; rg < 2; rg++)
            #pragma unroll
            for (int ng = 0; ng < 8; ng++) {
                int r = wm*32 + rg*16 + gr;
                int col = wn*64 + ng*8 + gc2;
                ep[r*132 + col]       = fmaxf(c[rg][ng][0] + qhs[col],     0.f);
                ep[r*132 + col + 1]   = fmaxf(c[rg][ng][1] + qhs[col + 1], 0.f);
                ep[(r+8)*132 + col]   = fmaxf(c[rg][ng][2] + qhs[col],     0.f);
                ep[(r+8)*132 + col+1] = fmaxf(c[rg][ng][3] + qhs[col + 1], 0.f);
            }
    } else {
        // path half: raw store to g_Cp
        #pragma unroll
        for (int rg = 0; rg < 2; rg++)
            #pragma unroll
            for (int ng = 0; ng < 8; ng++) {
                int r = wm*32 + rg*16 + gr;
                int pcol = (wn - 2)*64 + ng*8 + gc2;
                *(float2*)&g_Cp[(row0 + r)*Hh + pcol]     = make_float2(c[rg][ng][0], c[rg][ng][1]);
                *(float2*)&g_Cp[(row0 + r + 8)*Hh + pcol] = make_float2(c[rg][ng][2], c[rg][ng][3]);
            }
    }
    __syncthreads();

    // coin layer-2: 512 outputs = 64 rows x 8; 256 threads x 2
    #pragma unroll
    for (int it = 0; it < 2; it++) {
        int idx = it*256 + tid;
        int row = idx >> 3, j = idx & 7;
        float acc = b2s[j];
        #pragma unroll 8
        for (int h = 0; h < Hh; h++)
            acc = fmaf(ep[row*132 + h], w2s[h*KD + j], acc);
        g_amps[(row0 + row)*KD + j]  = acc;
        g_t[0][(row0 + row)*KD + j]  = acc * 0.00390625f;
    }
}

// ---------------------------------------------------------------------------
// One walk step, float4 over k. thread = (node, k-half). 128 nodes/block.
// Gathers t = prev_ns*amps (deferred normalization; see derivation in R5).
// ---------------------------------------------------------------------------
__global__ void walk_kernel(const int* __restrict__ nbrs, int step) {
    __shared__ int   nb[128*KN];
    __shared__ float red[256];
    int b  = blockIdx.y;
    int n0 = blockIdx.x * 128;
    int tid = threadIdx.x;

    const int4* nb_g = (const int4*)(nbrs + ((size_t)(b*Nn + n0))*KN);
    int4* nb4 = (int4*)nb;
    nb4[tid]       = nb_g[tid];
    nb4[tid + 256] = nb_g[tid + 256];

    float coef = 1.0f;
    if (step > 0) {
        red[tid] = (tid < 64) ? g_part[b*64 + tid] : 0.f;
        __syncthreads();
        for (int s = 128; s > 0; s >>= 1) {
            if (tid < s) red[tid] += red[tid + s];
            __syncthreads();
        }
        float ss = red[0];
        coef = (ss > 0.f) ? rsqrtf(ss) : 1.0f;
        __syncthreads();
    } else {
        __syncthreads();
    }

    int node = tid >> 1, kh = (tid & 1)*4;
    int n = n0 + node;
    const float* tb = g_t[step & 1] + (size_t)b*Nn*KD;

    float4 acc = *(const float4*)(tb + n*KD + kh);
    #pragma unroll
    for (int j = 0; j < KN; j++) {
        int idx = nb[node*KN + j];
        if (idx >= 0 && idx < Nn) {
            float4 v = *(const float4*)(tb + idx*KD + kh);
            acc.x += v.x; acc.y += v.y; acc.z += v.z; acc.w += v.w;
        }
    }
    float4 ns = make_float4(coef*acc.x, coef*acc.y, coef*acc.z, coef*acc.w);

    size_t gi = ((size_t)b*Nn + n)*KD + kh;
    if (step < STEPS - 1) {
        float4 am = *(const float4*)(g_amps + gi);
        *(float4*)(g_t[(step + 1) & 1] + gi) =
            make_float4(ns.x*am.x, ns.y*am.y, ns.z*am.z, ns.w*am.w);
    } else {
        *(float4*)(g_nsL + gi) = ns;
    }

    red[tid] = ns.x*ns.x + ns.y*ns.y + ns.z*ns.z + ns.w*ns.w;
    __syncthreads();
    for (int s = 128; s > 0; s >>= 1) {
        if (tid < s) red[tid] += red[tid + s];
        __syncthreads();
    }
    if (tid == 0) g_part[b*64 + blockIdx.x] = red[0];
}

// ---------------------------------------------------------------------------
// Final path MLP (inlines the last norm reduction).
// ---------------------------------------------------------------------------
__global__ void final_kernel(const float* __restrict__ pw1,
                             const float* __restrict__ w2, const float* __restrict__ b2,
                             float* __restrict__ out) {
    __shared__ float wst[KD*Hh];
    __shared__ float w2s[Hh];
    __shared__ float red[256];
    int tid = threadIdx.x;
    int b = blockIdx.x >> 10;   // 1024 blocks per batch

    for (int i = tid; i < KD*Hh; i += 256) wst[i] = pw1[(size_t)Dd*Hh + i];
    if (tid < Hh) w2s[tid] = w2[tid];
    red[tid] = (tid < 64) ? g_part[b*64 + tid] : 0.f;
    __syncthreads();
    for (int s = 128; s > 0; s >>= 1) {
        if (tid < s) red[tid] += red[tid + s];
        __syncthreads();
    }
    float ss = red[0];
    float inv = (ss > 0.f) ? rsqrtf(ss) : 1.0f;

    int r = blockIdx.x*8 + (tid >> 5);
    int l = tid & 31;

    const float* nsf = g_nsL + (size_t)r*KD;
    float s[KD];
    #pragma unroll
    for (int k = 0; k < KD; k++) s[k] = nsf[k] * inv;

    float4 cc = *(const float4*)&g_Cp[(size_t)r*Hh + l*4];
    float4 qv = *(const float4*)&g_qh[(Bb + b)*Hh + l*4];
    float hv[4] = { cc.x+qv.x, cc.y+qv.y, cc.z+qv.z, cc.w+qv.w };
    #pragma unroll
    for (int k = 0; k < KD; k++)
        #pragma unroll
        for (int i = 0; i < 4; i++)
            hv[i] = fmaf(s[k], wst[k*Hh + l*4 + i], hv[i]);

    float part = 0.f;
    #pragma unroll
    for (int i = 0; i < 4; i++) {
        float h = fmaxf(hv[i], 0.f);
        part = fmaf(h, w2s[l*4 + i], part);
    }
    #pragma unroll
    for (int m = 16; m > 0; m >>= 1)
        part += __shfl_xor_sync(0xffffffffu, part, m);
    if (l == 0) out[r] = part + b2[0];
}

// ---------------------------------------------------------------------------
extern "C" void kernel_launch(void* const* d_in, const int* in_sizes, int n_in,
                              void* d_out, int out_size) {
    const float* sent = (const float*)d_in[0];
    const float* q    = (const float*)d_in[1];
    const int*   nbrs = (const int*)  d_in[2];
    const float* cw1  = (const float*)d_in[3];
    const float* cb1  = (const float*)d_in[4];
    const float* cw2  = (const float*)d_in[5];
    const float* cb2  = (const float*)d_in[6];
    const float* pw1  = (const float*)d_in[7];
    const float* pb1  = (const float*)d_in[8];
    const float* pw2  = (const float*)d_in[9];
    const float* pb2  = (const float*)d_in[10];
    float* out = (float*)d_out;

    cudaFuncSetAttribute(gemm_hmma, cudaFuncAttributeMaxDynamicSharedMemorySize, SM_TOTAL);

    qh_kernel<<<dim3(Bb, 2), 512>>>(q, cw1, cb1, pw1, pb1);
    prepB_kernel<<<Dd, NB>>>(cw1, pw1);
    gemm_hmma<<<M_TOT/64, 256, SM_TOTAL>>>(sent, cw2, cb2);
    for (int s = 0; s < STEPS; s++)
        walk_kernel<<<dim3(Nn/128, Bb), 256>>>(nbrs, s);
    final_kernel<<<M_TOT/8, 256>>>(pw1, pw2, pb2, out);
}

// round 7
// speedup vs baseline: 1.1393x; 1.1393x over previous
#include <cuda_runtime.h>
#include <cuda_fp16.h>
#include <math.h>
#include <stdint.h>

#define Bb 16
#define Nn 8192
#define Dd 384
#define KN 16
#define KD 8
#define Hh 128
#define STEPS 3
#define M_TOT (Bb*Nn)   // 131072
#define NB 256          // fused weight width (coin 0..127 | path 128..255)

// GEMM: CTA 128 rows x 128 cols, K-chunk 16, 24 chunks, double buffered.
// per-buffer: A [0, 6144) (128 x APAD24 halves), B [6144, 10496) (16 x 136 halves)
#define SMBUF 10496
#define SM_TOTAL (2*SMBUF)   // 20992
// epilogue aliases within smem: part[128][2][8] @0 (8192), w2 @8192, qh @12288, b2 @12800

// ---- scratch (alloc-free: __device__ globals, fully rewritten every launch) ----
__device__ float g_Cp[(size_t)M_TOT*Hh];      // path hidden pre-act (sent part)   64MB
__device__ float g_amps[M_TOT*KD];            // coin amplitudes                    4MB
__device__ float g_t[2][M_TOT*KD];            // walk gather arrays               2x4MB
__device__ float g_nsL[M_TOT*KD];             // last step raw ns                   4MB
__device__ float g_qh[2*Bb*Hh];               // per-batch q@W + bias (coin, path)
__device__ float g_part[Bb*64];               // per-block sumsq partials
__device__ __half g_Bh[Dd*NB];                // fused W1, fp16, [k/16][k%16][n]

// ================= helpers =================
__device__ __forceinline__ uint32_t smem_u32(const void* p) {
    uint32_t a;
    asm("{ .reg .u64 t; cvta.to.shared.u64 t, %1; cvt.u32.u64 %0, t; }" : "=r"(a) : "l"(p));
    return a;
}
__device__ __forceinline__ void ldsm4(unsigned &r0, unsigned &r1, unsigned &r2, unsigned &r3,
                                      unsigned addr) {
    asm volatile("ldmatrix.sync.aligned.m8n8.x4.shared.b16 {%0,%1,%2,%3}, [%4];"
                 : "=r"(r0), "=r"(r1), "=r"(r2), "=r"(r3) : "r"(addr));
}
__device__ __forceinline__ void ldsm4t(unsigned &r0, unsigned &r1, unsigned &r2, unsigned &r3,
                                       unsigned addr) {
    asm volatile("ldmatrix.sync.aligned.m8n8.x4.trans.shared.b16 {%0,%1,%2,%3}, [%4];"
                 : "=r"(r0), "=r"(r1), "=r"(r2), "=r"(r3) : "r"(addr));
}
__device__ __forceinline__ void mma16816(float* c, const unsigned* a, unsigned b0, unsigned b1) {
    asm volatile(
        "mma.sync.aligned.m16n8k16.row.col.f32.f16.f16.f32 "
        "{%0,%1,%2,%3}, {%4,%5,%6,%7}, {%8,%9}, {%0,%1,%2,%3};"
        : "+f"(c[0]), "+f"(c[1]), "+f"(c[2]), "+f"(c[3])
        : "r"(a[0]), "r"(a[1]), "r"(a[2]), "r"(a[3]), "r"(b0), "r"(b1));
}
__device__ __forceinline__ uint32_t pack_h2(__half a, __half b) {
    __half2 t; t.x = a; t.y = b;
    return *(uint32_t*)&t;
}

// ---------------------------------------------------------------------------
// per-batch q contribution, parallel over k-chunks: 512 threads = 128 h x 4 kc
// ---------------------------------------------------------------------------
__global__ void qh_kernel(const float* __restrict__ q,
                          const float* __restrict__ cw1, const float* __restrict__ cb1,
                          const float* __restrict__ pw1, const float* __restrict__ pb1) {
    __shared__ float red[4][Hh];
    int b = blockIdx.x, which = blockIdx.y;
    int h = threadIdx.x & 127, kc = threadIdx.x >> 7;
    const float* w1   = which ? pw1 : cw1;
    const float* bias = which ? pb1 : cb1;
    int rowoff = which ? (Dd + KD) : Dd;
    const float* qb = q + b*Dd;
    float acc = 0.f;
    #pragma unroll 4
    for (int k = kc*96; k < kc*96 + 96; k++)
        acc = fmaf(qb[k], w1[(size_t)(rowoff + k)*Hh + h], acc);
    red[kc][h] = acc;
    __syncthreads();
    if (kc == 0)
        g_qh[(which*Bb + b)*Hh + h] = bias[h] + ((red[0][h] + red[1][h])
                                              +  (red[2][h] + red[3][h]));
}

// ---------------------------------------------------------------------------
// pre-convert fused W1 sent-block to fp16, layout [k/16][k%16][n] (n<128 coin)
// ---------------------------------------------------------------------------
__global__ void prepB_kernel(const float* __restrict__ cw1, const float* __restrict__ pw1) {
    int k = blockIdx.x;          // 0..383
    int n = threadIdx.x;         // 0..255
    const float* w = (n < Hh) ? cw1 : pw1;
    float v = w[(size_t)k*Hh + (n & (Hh-1))];
    g_Bh[(k >> 4)*(16*NB) + (k & 15)*NB + n] = __float2half_rn(v);
}

// ---------------------------------------------------------------------------
// HMMA GEMM: CTA = 128 rows x 128 cols (which = bid&1: 0 coin, 1 path),
// K=384 in 24 chunks of 16, fp16 single pass, fp32 accum, double-buffered
// smem + 2-deep register prefetch, 2 CTAs/SM. 8 warps = 4(M) x 2(N).
// Coin CTAs fuse layer-2 via quad-shuffle partials -> g_amps, g_t[0].
// Path CTAs store raw pre-act -> g_Cp.
// ---------------------------------------------------------------------------
__global__ void __launch_bounds__(256, 2)
gemm_hmma(const float* __restrict__ A,
          const float* __restrict__ cw2, const float* __restrict__ cb2) {
    __shared__ char smem[SM_TOTAL];
    const uint32_t sbase = smem_u32(smem);
    const int tid = threadIdx.x, lane = tid & 31, wid = tid >> 5;
    const int wm = wid >> 1, wn = wid & 1;
    const int which = blockIdx.x & 1;
    const size_t row0 = (size_t)(blockIdx.x >> 1) * 128;

    float c[2][8][4];
    #pragma unroll
    for (int i = 0; i < 2; i++)
        #pragma unroll
        for (int j = 0; j < 8; j++)
            #pragma unroll
            for (int l = 0; l < 4; l++) c[i][j][l] = 0.f;

    // A load: thread -> (row = tid>>1, 8 floats at col8 = (tid&1)*8)
    const int arow = tid >> 1, acol8 = (tid & 1)*8;
    const float* Ap = A + (row0 + arow)*Dd + acol8;
    const uint32_t a_sts = (uint32_t)arow*48 + (uint32_t)acol8*2;
    // B load: thread -> (krow = tid>>4, 8 halves at ncol8 = (tid&15)*8)
    const int bkrow = tid >> 4, bn8 = (tid & 15)*8;
    const int b_src0 = bkrow*NB + which*Hh + bn8;
    const uint32_t b_sts = 6144u + (uint32_t)bkrow*272 + (uint32_t)bn8*2;

    // ldmatrix lane offsets
    const uint32_t a_lane = (uint32_t)(lane & 15)*48 + (uint32_t)(lane >> 4)*16;
    const uint32_t b_lane = 6144u + (uint32_t)((lane & 7) + ((lane >> 3) & 1)*8)*272
                          + (uint32_t)(wn*64 + (lane >> 4)*8)*2;

    float4 sA[2][2]; uint4 sB[2];

    #define LDG_CHUNK(slot, ch) do {                                           \
        sA[slot][0] = *(const float4*)(Ap + (ch)*16);                          \
        sA[slot][1] = *(const float4*)(Ap + (ch)*16 + 4);                      \
        sB[slot]    = *(const uint4*)(g_Bh + (ch)*4096 + b_src0);              \
    } while (0)

    #define STS_CHUNK(bufbyte, slot) do {                                     \
        char* _bc = smem + (bufbyte);                                          \
        float _v[8] = {sA[slot][0].x, sA[slot][0].y, sA[slot][0].z, sA[slot][0].w, \
                       sA[slot][1].x, sA[slot][1].y, sA[slot][1].z, sA[slot][1].w};\
        uint32_t _p[4];                                                        \
        _Pragma("unroll")                                                      \
        for (int _i = 0; _i < 4; _i++)                                         \
            _p[_i] = pack_h2(__float2half_rn(_v[2*_i]),                        \
                             __float2half_rn(_v[2*_i+1]));                     \
        *(uint4*)(_bc + a_sts) = make_uint4(_p[0], _p[1], _p[2], _p[3]);       \
        *(uint4*)(_bc + b_sts) = sB[slot];                                     \
    } while (0)

    LDG_CHUNK(0, 0);
    STS_CHUNK(0, 0);
    LDG_CHUNK(1, 1);
    LDG_CHUNK(0, 2);
    __syncthreads();

    for (int ch = 0; ch < 24; ch++) {
        const int cur = ch & 1, nxt = cur ^ 1;
        {
            const uint32_t sb0 = sbase + (uint32_t)cur*SMBUF;
            unsigned af[2][4];
            #pragma unroll
            for (int rg = 0; rg < 2; rg++)
                ldsm4(af[rg][0], af[rg][1], af[rg][2], af[rg][3],
                      sb0 + (uint32_t)((wm*32 + rg*16)*48) + a_lane);
            #pragma unroll
            for (int pr = 0; pr < 4; pr++) {
                unsigned b0, b1, b2_, b3;
                ldsm4t(b0, b1, b2_, b3, sb0 + b_lane + (uint32_t)pr*32);
                #pragma unroll
                for (int rg = 0; rg < 2; rg++) {
                    mma16816(c[rg][2*pr],     af[rg], b0,  b1);
                    mma16816(c[rg][2*pr + 1], af[rg], b2_, b3);
                }
            }
        }
        if (ch < 23) STS_CHUNK((uint32_t)nxt*SMBUF, nxt & 1);
        if (ch + 3 < 24) LDG_CHUNK(nxt & 1, ch + 3);
        __syncthreads();
    }

    const int gr = lane >> 2, gq = lane & 3, gc2 = gq*2;

    if (which == 1) {
        // path: raw store to g_Cp
        #pragma unroll
        for (int rg = 0; rg < 2; rg++)
            #pragma unroll
            for (int ng = 0; ng < 8; ng++) {
                int r = wm*32 + rg*16 + gr;
                int pcol = wn*64 + ng*8 + gc2;
                *(float2*)&g_Cp[(row0 + r)*Hh + pcol]     = make_float2(c[rg][ng][0], c[rg][ng][1]);
                *(float2*)&g_Cp[(row0 + r + 8)*Hh + pcol] = make_float2(c[rg][ng][2], c[rg][ng][3]);
            }
        return;
    }

    // ---- coin epilogue: layer-2 via quad-shuffle partials ----
    const int b = blockIdx.x >> 7;            // 64 tiles * 2 per batch
    float* part = (float*)smem;               // [128][2][8]
    float* w2s  = (float*)(smem + 8192);      // [128*8]
    float* qhs  = (float*)(smem + 12288);     // [128]
    float* b2s  = (float*)(smem + 12800);     // [8]
    for (int i = tid; i < Hh*KD; i += 256) w2s[i] = cw2[i];
    if (tid < Hh) qhs[tid] = g_qh[b*Hh + tid];
    if (tid < KD) b2s[tid] = cb2[tid];
    __syncthreads();

    #pragma unroll
    for (int rg = 0; rg < 2; rg++) {
        float pa[8], pb[8];
        #pragma unroll
        for (int j = 0; j < 8; j++) { pa[j] = 0.f; pb[j] = 0.f; }
        #pragma unroll
        for (int ng = 0; ng < 8; ng++) {
            int col = wn*64 + ng*8 + gc2;
            float qa = qhs[col], qb = qhs[col + 1];
            float h0 = fmaxf(c[rg][ng][0] + qa, 0.f);
            float h1 = fmaxf(c[rg][ng][1] + qb, 0.f);
            float h2 = fmaxf(c[rg][ng][2] + qa, 0.f);
            float h3 = fmaxf(c[rg][ng][3] + qb, 0.f);
            #pragma unroll
            for (int j = 0; j < 8; j++) {
                float w0 = w2s[col*8 + j], w1 = w2s[(col + 1)*8 + j];
                pa[j] += h0*w0 + h1*w1;
                pb[j] += h2*w0 + h3*w1;
            }
        }
        #pragma unroll
        for (int j = 0; j < 8; j++) {
            pa[j] += __shfl_xor_sync(0xffffffffu, pa[j], 1);
            pa[j] += __shfl_xor_sync(0xffffffffu, pa[j], 2);
            pb[j] += __shfl_xor_sync(0xffffffffu, pb[j], 1);
            pb[j] += __shfl_xor_sync(0xffffffffu, pb[j], 2);
        }
        if (gq == 0) {
            int row = wm*32 + rg*16 + gr;
            #pragma unroll
            for (int j = 0; j < 8; j++) {
                part[(row*2 + wn)*8 + j]       = pa[j];
                part[((row + 8)*2 + wn)*8 + j] = pb[j];
            }
        }
    }
    __syncthreads();

    #pragma unroll
    for (int it = 0; it < 4; it++) {
        int idx = it*256 + tid;
        int row = idx >> 3, j = idx & 7;
        float acc = b2s[j] + part[(row*2)*8 + j] + part[(row*2 + 1)*8 + j];
        g_amps[(row0 + row)*KD + j] = acc;
        g_t[0][(row0 + row)*KD + j] = acc * 0.00390625f;
    }
}

// ---------------------------------------------------------------------------
// One walk step, float4 over k. thread = (node, k-half). 128 nodes/block.
// ---------------------------------------------------------------------------
__global__ void walk_kernel(const int* __restrict__ nbrs, int step) {
    __shared__ int   nb[128*KN];
    __shared__ float red[256];
    int b  = blockIdx.y;
    int n0 = blockIdx.x * 128;
    int tid = threadIdx.x;

    const int4* nb_g = (const int4*)(nbrs + ((size_t)(b*Nn + n0))*KN);
    int4* nb4 = (int4*)nb;
    nb4[tid]       = nb_g[tid];
    nb4[tid + 256] = nb_g[tid + 256];

    float coef = 1.0f;
    if (step > 0) {
        red[tid] = (tid < 64) ? g_part[b*64 + tid] : 0.f;
        __syncthreads();
        for (int s = 128; s > 0; s >>= 1) {
            if (tid < s) red[tid] += red[tid + s];
            __syncthreads();
        }
        float ss = red[0];
        coef = (ss > 0.f) ? rsqrtf(ss) : 1.0f;
        __syncthreads();
    } else {
        __syncthreads();
    }

    int node = tid >> 1, kh = (tid & 1)*4;
    int n = n0 + node;
    const float* tb = g_t[step & 1] + (size_t)b*Nn*KD;

    float4 acc = *(const float4*)(tb + n*KD + kh);
    #pragma unroll
    for (int j = 0; j < KN; j++) {
        int idx = nb[node*KN + j];
        if (idx >= 0 && idx < Nn) {
            float4 v = *(const float4*)(tb + idx*KD + kh);
            acc.x += v.x; acc.y += v.y; acc.z += v.z; acc.w += v.w;
        }
    }
    float4 ns = make_float4(coef*acc.x, coef*acc.y, coef*acc.z, coef*acc.w);

    size_t gi = ((size_t)b*Nn + n)*KD + kh;
    if (step < STEPS - 1) {
        float4 am = *(const float4*)(g_amps + gi);
        *(float4*)(g_t[(step + 1) & 1] + gi) =
            make_float4(ns.x*am.x, ns.y*am.y, ns.z*am.z, ns.w*am.w);
    } else {
        *(float4*)(g_nsL + gi) = ns;
    }

    red[tid] = ns.x*ns.x + ns.y*ns.y + ns.z*ns.z + ns.w*ns.w;
    __syncthreads();
    for (int s = 128; s > 0; s >>= 1) {
        if (tid < s) red[tid] += red[tid + s];
        __syncthreads();
    }
    if (tid == 0) g_part[b*64 + blockIdx.x] = red[0];
}

// ---------------------------------------------------------------------------
// Final path MLP (inlines the last norm reduction).
// ---------------------------------------------------------------------------
__global__ void final_kernel(const float* __restrict__ pw1,
                             const float* __restrict__ w2, const float* __restrict__ b2,
                             float* __restrict__ out) {
    __shared__ float wst[KD*Hh];
    __shared__ float w2s[Hh];
    __shared__ float red[256];
    int tid = threadIdx.x;
    int b = blockIdx.x >> 10;   // 1024 blocks per batch

    for (int i = tid; i < KD*Hh; i += 256) wst[i] = pw1[(size_t)Dd*Hh + i];
    if (tid < Hh) w2s[tid] = w2[tid];
    red[tid] = (tid < 64) ? g_part[b*64 + tid] : 0.f;
    __syncthreads();
    for (int s = 128; s > 0; s >>= 1) {
        if (tid < s) red[tid] += red[tid + s];
        __syncthreads();
    }
    float ss = red[0];
    float inv = (ss > 0.f) ? rsqrtf(ss) : 1.0f;

    int r = blockIdx.x*8 + (tid >> 5);
    int l = tid & 31;

    const float* nsf = g_nsL + (size_t)r*KD;
    float s[KD];
    #pragma unroll
    for (int k = 0; k < KD; k++) s[k] = nsf[k] * inv;

    float4 cc = *(const float4*)&g_Cp[(size_t)r*Hh + l*4];
    float4 qv = *(const float4*)&g_qh[(Bb + b)*Hh + l*4];
    float hv[4] = { cc.x+qv.x, cc.y+qv.y, cc.z+qv.z, cc.w+qv.w };
    #pragma unroll
    for (int k = 0; k < KD; k++)
        #pragma unroll
        for (int i = 0; i < 4; i++)
            hv[i] = fmaf(s[k], wst[k*Hh + l*4 + i], hv[i]);

    float part = 0.f;
    #pragma unroll
    for (int i = 0; i < 4; i++) {
        float h = fmaxf(hv[i], 0.f);
        part = fmaf(h, w2s[l*4 + i], part);
    }
    #pragma unroll
    for (int m = 16; m > 0; m >>= 1)
        part += __shfl_xor_sync(0xffffffffu, part, m);
    if (l == 0) out[r] = part + b2[0];
}

// ---------------------------------------------------------------------------
extern "C" void kernel_launch(void* const* d_in, const int* in_sizes, int n_in,
                              void* d_out, int out_size) {
    const float* sent = (const float*)d_in[0];
    const float* q    = (const float*)d_in[1];
    const int*   nbrs = (const int*)  d_in[2];
    const float* cw1  = (const float*)d_in[3];
    const float* cb1  = (const float*)d_in[4];
    const float* cw2  = (const float*)d_in[5];
    const float* cb2  = (const float*)d_in[6];
    const float* pw1  = (const float*)d_in[7];
    const float* pb1  = (const float*)d_in[8];
    const float* pw2  = (const float*)d_in[9];
    const float* pb2  = (const float*)d_in[10];
    float* out = (float*)d_out;

    qh_kernel<<<dim3(Bb, 2), 512>>>(q, cw1, cb1, pw1, pb1);
    prepB_kernel<<<Dd, NB>>>(cw1, pw1);
    gemm_hmma<<<(M_TOT/128)*2, 256>>>(sent, cw2, cb2);
    for (int s = 0; s < STEPS; s++)
        walk_kernel<<<dim3(Nn/128, Bb), 256>>>(nbrs, s);
    final_kernel<<<M_TOT/8, 256>>>(pw1, pw2, pb2, out);
}

// round 8
// speedup vs baseline: 1.2852x; 1.1281x over previous
#include <cuda_runtime.h>
#include <cuda_fp16.h>
#include <math.h>
#include <stdint.h>

#define Bb 16
#define Nn 8192
#define Dd 384
#define KN 16
#define KD 8
#define Hh 128
#define STEPS 3
#define M_TOT (Bb*Nn)   // 131072
#define NB 256          // fused weight width (coin 0..127 | path 128..255)

// GEMM: CTA 128 rows x 128 cols, K-chunk 48, 8 chunks, 3-stage pipeline.
#define KC 48
#define NCH 8
#define A_STRIDE 112                 // bytes per A smem row (7 x 16B)
#define A_BYTES (128*A_STRIDE)       // 14336
#define B_STRIDE 272                 // bytes per B smem row (17 x 16B)
#define B_BYTES (KC*B_STRIDE)        // 13056
#define SMBUF (A_BYTES + B_BYTES)    // 27392
#define SM_TOTAL (3*SMBUF)           // 82176

// ---- scratch (alloc-free: __device__ globals, fully rewritten every launch) ----
__device__ float g_Cp[(size_t)M_TOT*Hh];      // path hidden pre-act (sent part)   64MB
__device__ float g_amps[M_TOT*KD];            // coin amplitudes                    4MB
__device__ float g_t[2][M_TOT*KD];            // walk gather arrays               2x4MB
__device__ float g_nsL[M_TOT*KD];             // last step raw ns                   4MB
__device__ float g_qh[2*Bb*Hh];               // per-batch q@W + bias (coin, path)
__device__ float g_part[Bb*64];               // per-block sumsq partials
__device__ __half g_Bh[Dd*NB];                // fused W1, fp16, [k/16][k%16][n]

// ================= helpers =================
__device__ __forceinline__ uint32_t smem_u32(const void* p) {
    uint32_t a;
    asm("{ .reg .u64 t; cvta.to.shared.u64 t, %1; cvt.u32.u64 %0, t; }" : "=r"(a) : "l"(p));
    return a;
}
__device__ __forceinline__ void ldsm4(unsigned &r0, unsigned &r1, unsigned &r2, unsigned &r3,
                                      unsigned addr) {
    asm volatile("ldmatrix.sync.aligned.m8n8.x4.shared.b16 {%0,%1,%2,%3}, [%4];"
                 : "=r"(r0), "=r"(r1), "=r"(r2), "=r"(r3) : "r"(addr));
}
__device__ __forceinline__ void ldsm4t(unsigned &r0, unsigned &r1, unsigned &r2, unsigned &r3,
                                       unsigned addr) {
    asm volatile("ldmatrix.sync.aligned.m8n8.x4.trans.shared.b16 {%0,%1,%2,%3}, [%4];"
                 : "=r"(r0), "=r"(r1), "=r"(r2), "=r"(r3) : "r"(addr));
}
__device__ __forceinline__ void mma16816(float* c, const unsigned* a, unsigned b0, unsigned b1) {
    asm volatile(
        "mma.sync.aligned.m16n8k16.row.col.f32.f16.f16.f32 "
        "{%0,%1,%2,%3}, {%4,%5,%6,%7}, {%8,%9}, {%0,%1,%2,%3};"
        : "+f"(c[0]), "+f"(c[1]), "+f"(c[2]), "+f"(c[3])
        : "r"(a[0]), "r"(a[1]), "r"(a[2]), "r"(a[3]), "r"(b0), "r"(b1));
}
__device__ __forceinline__ uint32_t pack_h2(__half a, __half b) {
    __half2 t; t.x = a; t.y = b;
    return *(uint32_t*)&t;
}
__device__ __forceinline__ void cp16(uint32_t dst, const void* src) {
    asm volatile("cp.async.cg.shared.global [%0], [%1], 16;" :: "r"(dst), "l"(src));
}

// ---------------------------------------------------------------------------
// per-batch q contribution, parallel over k-chunks: 512 threads = 128 h x 4 kc
// ---------------------------------------------------------------------------
__global__ void qh_kernel(const float* __restrict__ q,
                          const float* __restrict__ cw1, const float* __restrict__ cb1,
                          const float* __restrict__ pw1, const float* __restrict__ pb1) {
    __shared__ float red[4][Hh];
    int b = blockIdx.x, which = blockIdx.y;
    int h = threadIdx.x & 127, kc = threadIdx.x >> 7;
    const float* w1   = which ? pw1 : cw1;
    const float* bias = which ? pb1 : cb1;
    int rowoff = which ? (Dd + KD) : Dd;
    const float* qb = q + b*Dd;
    float acc = 0.f;
    #pragma unroll 4
    for (int k = kc*96; k < kc*96 + 96; k++)
        acc = fmaf(qb[k], w1[(size_t)(rowoff + k)*Hh + h], acc);
    red[kc][h] = acc;
    __syncthreads();
    if (kc == 0)
        g_qh[(which*Bb + b)*Hh + h] = bias[h] + ((red[0][h] + red[1][h])
                                              +  (red[2][h] + red[3][h]));
}

// ---------------------------------------------------------------------------
// pre-convert fused W1 sent-block to fp16 (sliced into 4 launches so the GEMM
// is the 6th launch -> ncu -s 5 -c 1 profiles the GEMM)
// ---------------------------------------------------------------------------
__global__ void prepB_kernel(const float* __restrict__ cw1, const float* __restrict__ pw1,
                             int koff) {
    int k = koff + blockIdx.x;   // 96 blocks per slice
    int n = threadIdx.x;         // 0..255
    const float* w = (n < Hh) ? cw1 : pw1;
    float v = w[(size_t)k*Hh + (n & (Hh-1))];
    g_Bh[(k >> 4)*(16*NB) + (k & 15)*NB + n] = __float2half_rn(v);
}

// ---------------------------------------------------------------------------
// HMMA GEMM: CTA = 128 rows x 128 cols (which = bid&1: 0 coin, 1 path),
// K=384 in 8 chunks of 48, fp16 single pass, fp32 accum.
// 3-stage smem pipeline; B via cp.async (no reg staging); A LDG->cvt->STS.
// 8 warps = 4(M) x 2(N), 2 CTAs/SM.
// ---------------------------------------------------------------------------
__global__ void __launch_bounds__(256, 2)
gemm_hmma(const float* __restrict__ A,
          const float* __restrict__ cw2, const float* __restrict__ cb2) {
    extern __shared__ char smem[];
    const uint32_t sbase = smem_u32(smem);
    const int tid = threadIdx.x, lane = tid & 31, wid = tid >> 5;
    const int wm = wid >> 1, wn = wid & 1;
    const int which = blockIdx.x & 1;
    const size_t row0 = (size_t)(blockIdx.x >> 1) * 128;

    float c[2][8][4];
    #pragma unroll
    for (int i = 0; i < 2; i++)
        #pragma unroll
        for (int j = 0; j < 8; j++)
            #pragma unroll
            for (int l = 0; l < 4; l++) c[i][j][l] = 0.f;

    // A: thread -> (row = tid>>1, 24 floats at ahalf*24)
    const int arow = tid >> 1, ahalf = tid & 1;
    const float* Ap = A + (row0 + arow)*Dd + ahalf*24;
    const uint32_t a_sts = (uint32_t)arow*A_STRIDE + (uint32_t)ahalf*48;
    // B: thread -> rows {brow, brow+16, brow+32}, 8 halves at bn8
    const int brow = tid >> 4, bn8 = (tid & 15)*8;
    const int b_src0 = brow*NB + which*Hh + bn8;
    const uint32_t b_sts0 = A_BYTES + (uint32_t)brow*B_STRIDE + (uint32_t)bn8*2;

    // ldmatrix lane offsets
    const uint32_t a_lane = (uint32_t)(lane & 15)*A_STRIDE + (uint32_t)(lane >> 4)*16;
    const uint32_t b_lane = (uint32_t)((lane & 7) + ((lane >> 3) & 1)*8)*B_STRIDE
                          + (uint32_t)(wn*64 + (lane >> 4)*8)*2;

    float4 areg[6];

    #define LDG_A(ch) do {                                                     \
        _Pragma("unroll")                                                      \
        for (int _i = 0; _i < 6; _i++)                                         \
            areg[_i] = *(const float4*)(Ap + (ch)*KC + _i*4);                  \
    } while (0)

    #define STS_A(bufbyte) do {                                               \
        char* _bc = smem + (bufbyte);                                          \
        _Pragma("unroll")                                                      \
        for (int _g = 0; _g < 3; _g++) {                                       \
            float _v[8] = {areg[2*_g].x, areg[2*_g].y, areg[2*_g].z, areg[2*_g].w, \
                           areg[2*_g+1].x, areg[2*_g+1].y, areg[2*_g+1].z, areg[2*_g+1].w}; \
            uint32_t _p[4];                                                    \
            _Pragma("unroll")                                                  \
            for (int _i = 0; _i < 4; _i++)                                     \
                _p[_i] = pack_h2(__float2half_rn(_v[2*_i]),                    \
                                 __float2half_rn(_v[2*_i+1]));                 \
            *(uint4*)(_bc + a_sts + _g*16) = make_uint4(_p[0], _p[1], _p[2], _p[3]); \
        }                                                                      \
    } while (0)

    #define CP_B(ch, bufbyte) do {                                            \
        _Pragma("unroll")                                                      \
        for (int _j = 0; _j < 3; _j++)                                         \
            cp16(sbase + (bufbyte) + b_sts0 + (uint32_t)_j*16*B_STRIDE,        \
                 g_Bh + ((ch)*3 + _j)*4096 + b_src0);                          \
        asm volatile("cp.async.commit_group;" ::: "memory");                   \
    } while (0)

    // prologue: buf0 <- chunk0, buf1 <- B(1) in flight
    LDG_A(0);
    CP_B(0, 0);
    CP_B(1, SMBUF);
    STS_A(0);
    asm volatile("cp.async.wait_group 1;" ::: "memory");
    __syncthreads();

    for (int ch = 0; ch < NCH; ch++) {
        const uint32_t bufc = (uint32_t)(ch % 3)*SMBUF;
        if (ch + 1 < NCH) LDG_A(ch + 1);
        // ---- MMA on buffer cur ----
        {
            const uint32_t sb0 = sbase + bufc;
            #pragma unroll
            for (int s = 0; s < 3; s++) {
                unsigned af[2][4];
                #pragma unroll
                for (int rg = 0; rg < 2; rg++)
                    ldsm4(af[rg][0], af[rg][1], af[rg][2], af[rg][3],
                          sb0 + (uint32_t)((wm*32 + rg*16)*A_STRIDE) + a_lane
                              + (uint32_t)s*32);
                #pragma unroll
                for (int pr = 0; pr < 4; pr++) {
                    unsigned b0, b1, b2_, b3;
                    ldsm4t(b0, b1, b2_, b3,
                           sb0 + A_BYTES + (uint32_t)s*(16*B_STRIDE)
                               + (uint32_t)pr*32 + b_lane);
                    #pragma unroll
                    for (int rg = 0; rg < 2; rg++) {
                        mma16816(c[rg][2*pr],     af[rg], b0,  b1);
                        mma16816(c[rg][2*pr + 1], af[rg], b2_, b3);
                    }
                }
            }
        }
        if (ch + 1 < NCH) STS_A((uint32_t)((ch + 1) % 3)*SMBUF);
        if (ch + 2 < NCH) {
            CP_B(ch + 2, (uint32_t)((ch + 2) % 3)*SMBUF);
            asm volatile("cp.async.wait_group 1;" ::: "memory");
        } else {
            asm volatile("cp.async.wait_group 0;" ::: "memory");
        }
        __syncthreads();
    }

    const int gr = lane >> 2, gq = lane & 3, gc2 = gq*2;

    if (which == 1) {
        // path: raw store to g_Cp
        #pragma unroll
        for (int rg = 0; rg < 2; rg++)
            #pragma unroll
            for (int ng = 0; ng < 8; ng++) {
                int r = wm*32 + rg*16 + gr;
                int pcol = wn*64 + ng*8 + gc2;
                *(float2*)&g_Cp[(row0 + r)*Hh + pcol]     = make_float2(c[rg][ng][0], c[rg][ng][1]);
                *(float2*)&g_Cp[(row0 + r + 8)*Hh + pcol] = make_float2(c[rg][ng][2], c[rg][ng][3]);
            }
        return;
    }

    // ---- coin epilogue: layer-2 via quad-shuffle partials ----
    const int b = blockIdx.x >> 7;            // 64 tiles * 2 per batch
    float* part = (float*)smem;               // [128][2][8]
    float* w2s  = (float*)(smem + 8192);      // [128*8]
    float* qhs  = (float*)(smem + 12288);     // [128]
    float* b2s  = (float*)(smem + 12800);     // [8]
    for (int i = tid; i < Hh*KD; i += 256) w2s[i] = cw2[i];
    if (tid < Hh) qhs[tid] = g_qh[b*Hh + tid];
    if (tid < KD) b2s[tid] = cb2[tid];
    __syncthreads();

    #pragma unroll
    for (int rg = 0; rg < 2; rg++) {
        float pa[8], pb[8];
        #pragma unroll
        for (int j = 0; j < 8; j++) { pa[j] = 0.f; pb[j] = 0.f; }
        #pragma unroll
        for (int ng = 0; ng < 8; ng++) {
            int col = wn*64 + ng*8 + gc2;
            float qa = qhs[col], qb = qhs[col + 1];
            float h0 = fmaxf(c[rg][ng][0] + qa, 0.f);
            float h1 = fmaxf(c[rg][ng][1] + qb, 0.f);
            float h2 = fmaxf(c[rg][ng][2] + qa, 0.f);
            float h3 = fmaxf(c[rg][ng][3] + qb, 0.f);
            #pragma unroll
            for (int j = 0; j < 8; j++) {
                float w0 = w2s[col*8 + j], w1 = w2s[(col + 1)*8 + j];
                pa[j] += h0*w0 + h1*w1;
                pb[j] += h2*w0 + h3*w1;
            }
        }
        #pragma unroll
        for (int j = 0; j < 8; j++) {
            pa[j] += __shfl_xor_sync(0xffffffffu, pa[j], 1);
            pa[j] += __shfl_xor_sync(0xffffffffu, pa[j], 2);
            pb[j] += __shfl_xor_sync(0xffffffffu, pb[j], 1);
            pb[j] += __shfl_xor_sync(0xffffffffu, pb[j], 2);
        }
        if (gq == 0) {
            int row = wm*32 + rg*16 + gr;
            #pragma unroll
            for (int j = 0; j < 8; j++) {
                part[(row*2 + wn)*8 + j]       = pa[j];
                part[((row + 8)*2 + wn)*8 + j] = pb[j];
            }
        }
    }
    __syncthreads();

    #pragma unroll
    for (int it = 0; it < 4; it++) {
        int idx = it*256 + tid;
        int row = idx >> 3, j = idx & 7;
        float acc = b2s[j] + part[(row*2)*8 + j] + part[(row*2 + 1)*8 + j];
        g_amps[(row0 + row)*KD + j] = acc;
        g_t[0][(row0 + row)*KD + j] = acc * 0.00390625f;
    }
}

// ---------------------------------------------------------------------------
// One walk step. Warp-level coef (no barriers); 2 barriers total.
// ---------------------------------------------------------------------------
__global__ void walk_kernel(const int* __restrict__ nbrs, int step) {
    __shared__ int   nb[128*KN];
    __shared__ float red[8];
    int b  = blockIdx.y;
    int n0 = blockIdx.x * 128;
    int tid = threadIdx.x, lane = tid & 31, wid = tid >> 5;

    const int4* nb_g = (const int4*)(nbrs + ((size_t)(b*Nn + n0))*KN);
    int4* nb4 = (int4*)nb;
    nb4[tid]       = nb_g[tid];
    nb4[tid + 256] = nb_g[tid + 256];

    float coef = 1.0f;
    if (step > 0) {
        float p = g_part[b*64 + lane] + g_part[b*64 + 32 + lane];
        #pragma unroll
        for (int m = 16; m > 0; m >>= 1) p += __shfl_xor_sync(0xffffffffu, p, m);
        coef = (p > 0.f) ? rsqrtf(p) : 1.0f;
    }
    __syncthreads();

    int node = tid >> 1, kh = (tid & 1)*4;
    int n = n0 + node;
    const float* tb = g_t[step & 1] + (size_t)b*Nn*KD;

    float4 acc = *(const float4*)(tb + n*KD + kh);
    #pragma unroll
    for (int j = 0; j < KN; j++) {
        int idx = nb[node*KN + j];
        if (idx >= 0 && idx < Nn) {
            float4 v = *(const float4*)(tb + idx*KD + kh);
            acc.x += v.x; acc.y += v.y; acc.z += v.z; acc.w += v.w;
        }
    }
    float4 ns = make_float4(coef*acc.x, coef*acc.y, coef*acc.z, coef*acc.w);

    size_t gi = ((size_t)b*Nn + n)*KD + kh;
    if (step < STEPS - 1) {
        float4 am = *(const float4*)(g_amps + gi);
        *(float4*)(g_t[(step + 1) & 1] + gi) =
            make_float4(ns.x*am.x, ns.y*am.y, ns.z*am.z, ns.w*am.w);
    } else {
        *(float4*)(g_nsL + gi) = ns;
    }

    float s = ns.x*ns.x + ns.y*ns.y + ns.z*ns.z + ns.w*ns.w;
    #pragma unroll
    for (int m = 16; m > 0; m >>= 1) s += __shfl_xor_sync(0xffffffffu, s, m);
    if (lane == 0) red[wid] = s;
    __syncthreads();
    if (tid == 0) {
        float t = 0.f;
        #pragma unroll
        for (int i = 0; i < 8; i++) t += red[i];
        g_part[b*64 + blockIdx.x] = t;
    }
}

// ---------------------------------------------------------------------------
// Final path MLP. Warp-level coef (no block reduce barriers).
// ---------------------------------------------------------------------------
__global__ void final_kernel(const float* __restrict__ pw1,
                             const float* __restrict__ w2, const float* __restrict__ b2,
                             float* __restrict__ out) {
    __shared__ float wst[KD*Hh];
    __shared__ float w2s[Hh];
    int tid = threadIdx.x, lane = tid & 31;
    int b = blockIdx.x >> 10;   // 1024 blocks per batch

    for (int i = tid; i < KD*Hh; i += 256) wst[i] = pw1[(size_t)Dd*Hh + i];
    if (tid < Hh) w2s[tid] = w2[tid];

    float p = g_part[b*64 + lane] + g_part[b*64 + 32 + lane];
    #pragma unroll
    for (int m = 16; m > 0; m >>= 1) p += __shfl_xor_sync(0xffffffffu, p, m);
    float inv = (p > 0.f) ? rsqrtf(p) : 1.0f;
    __syncthreads();

    int r = blockIdx.x*8 + (tid >> 5);
    int l = lane;

    const float* nsf = g_nsL + (size_t)r*KD;
    float s[KD];
    #pragma unroll
    for (int k = 0; k < KD; k++) s[k] = nsf[k] * inv;

    float4 cc = *(const float4*)&g_Cp[(size_t)r*Hh + l*4];
    float4 qv = *(const float4*)&g_qh[(Bb + b)*Hh + l*4];
    float hv[4] = { cc.x+qv.x, cc.y+qv.y, cc.z+qv.z, cc.w+qv.w };
    #pragma unroll
    for (int k = 0; k < KD; k++)
        #pragma unroll
        for (int i = 0; i < 4; i++)
            hv[i] = fmaf(s[k], wst[k*Hh + l*4 + i], hv[i]);

    float part = 0.f;
    #pragma unroll
    for (int i = 0; i < 4; i++) {
        float h = fmaxf(hv[i], 0.f);
        part = fmaf(h, w2s[l*4 + i], part);
    }
    #pragma unroll
    for (int m = 16; m > 0; m >>= 1)
        part += __shfl_xor_sync(0xffffffffu, part, m);
    if (l == 0) out[r] = part + b2[0];
}

// ---------------------------------------------------------------------------
extern "C" void kernel_launch(void* const* d_in, const int* in_sizes, int n_in,
                              void* d_out, int out_size) {
    const float* sent = (const float*)d_in[0];
    const float* q    = (const float*)d_in[1];
    const int*   nbrs = (const int*)  d_in[2];
    const float* cw1  = (const float*)d_in[3];
    const float* cb1  = (const float*)d_in[4];
    const float* cw2  = (const float*)d_in[5];
    const float* cb2  = (const float*)d_in[6];
    const float* pw1  = (const float*)d_in[7];
    const float* pb1  = (const float*)d_in[8];
    const float* pw2  = (const float*)d_in[9];
    const float* pb2  = (const float*)d_in[10];
    float* out = (float*)d_out;

    cudaFuncSetAttribute(gemm_hmma, cudaFuncAttributeMaxDynamicSharedMemorySize, SM_TOTAL);

    qh_kernel<<<dim3(Bb, 2), 512>>>(q, cw1, cb1, pw1, pb1);             // launch 1
    for (int s = 0; s < 4; s++)                                          // launches 2-5
        prepB_kernel<<<96, NB>>>(cw1, pw1, s*96);
    gemm_hmma<<<(M_TOT/128)*2, 256, SM_TOTAL>>>(sent, cw2, cb2);         // launch 6 (profiled)
    for (int s = 0; s < STEPS; s++)
        walk_kernel<<<dim3(Nn/128, Bb), 256>>>(nbrs, s);
    final_kernel<<<M_TOT/8, 256>>>(pw1, pw2, pb2, out);
}

// round 9
// speedup vs baseline: 1.4211x; 1.1058x over previous
#include <cuda_runtime.h>
#include <cuda_fp16.h>
#include <math.h>
#include <stdint.h>

#define Bb 16
#define Nn 8192
#define Dd 384
#define KN 16
#define KD 8
#define Hh 128
#define STEPS 3
#define M_TOT (Bb*Nn)   // 131072
#define NB 256          // fused weight width (coin 0..127 | path 128..255)

// GEMM: CTA 128 rows x 128 cols, K-chunk 48, 8 chunks, 3-stage pipeline.
#define KC 48
#define NCH 8
#define A_STRIDE 112                 // bytes per A smem row (7 x 16B)
#define A_BYTES (128*A_STRIDE)       // 14336
#define B_STRIDE 272                 // bytes per B smem row (17 x 16B)
#define B_BYTES (KC*B_STRIDE)        // 13056
#define SMBUF (A_BYTES + B_BYTES)    // 27392
#define SM_TOTAL (3*SMBUF)           // 82176

// ---- scratch (alloc-free: __device__ globals, fully rewritten every launch) ----
__device__ float g_Cp[(size_t)M_TOT*Hh];      // path hidden pre-act (sent part)   64MB
__device__ float g_amps[M_TOT*KD];            // coin amplitudes                    4MB
__device__ float g_t[2][M_TOT*KD];            // walk gather arrays               2x4MB
__device__ float g_nsL[M_TOT*KD];             // last step raw ns                   4MB
__device__ float g_qh[2*Bb*Hh];               // per-batch q@W + bias (coin, path)
__device__ float g_part[Bb*64];               // per-block sumsq partials
__device__ __half g_Bh[Dd*NB];                // fused W1, fp16, [k/16][k%16][n]

// ================= helpers =================
__device__ __forceinline__ uint32_t smem_u32(const void* p) {
    uint32_t a;
    asm("{ .reg .u64 t; cvta.to.shared.u64 t, %1; cvt.u32.u64 %0, t; }" : "=r"(a) : "l"(p));
    return a;
}
__device__ __forceinline__ void ldsm4(unsigned &r0, unsigned &r1, unsigned &r2, unsigned &r3,
                                      unsigned addr) {
    asm volatile("ldmatrix.sync.aligned.m8n8.x4.shared.b16 {%0,%1,%2,%3}, [%4];"
                 : "=r"(r0), "=r"(r1), "=r"(r2), "=r"(r3) : "r"(addr));
}
__device__ __forceinline__ void ldsm4t(unsigned &r0, unsigned &r1, unsigned &r2, unsigned &r3,
                                       unsigned addr) {
    asm volatile("ldmatrix.sync.aligned.m8n8.x4.trans.shared.b16 {%0,%1,%2,%3}, [%4];"
                 : "=r"(r0), "=r"(r1), "=r"(r2), "=r"(r3) : "r"(addr));
}
__device__ __forceinline__ void mma16816(float* c, const unsigned* a, unsigned b0, unsigned b1) {
    asm volatile(
        "mma.sync.aligned.m16n8k16.row.col.f32.f16.f16.f32 "
        "{%0,%1,%2,%3}, {%4,%5,%6,%7}, {%8,%9}, {%0,%1,%2,%3};"
        : "+f"(c[0]), "+f"(c[1]), "+f"(c[2]), "+f"(c[3])
        : "r"(a[0]), "r"(a[1]), "r"(a[2]), "r"(a[3]), "r"(b0), "r"(b1));
}
__device__ __forceinline__ uint32_t pack_h2(__half a, __half b) {
    __half2 t; t.x = a; t.y = b;
    return *(uint32_t*)&t;
}
__device__ __forceinline__ void cp16(uint32_t dst, const void* src) {
    asm volatile("cp.async.cg.shared.global [%0], [%1], 16;" :: "r"(dst), "l"(src));
}

// ---------------------------------------------------------------------------
// per-batch q contribution, parallel over k-chunks: 512 threads = 128 h x 4 kc
// ---------------------------------------------------------------------------
__global__ void qh_kernel(const float* __restrict__ q,
                          const float* __restrict__ cw1, const float* __restrict__ cb1,
                          const float* __restrict__ pw1, const float* __restrict__ pb1) {
    __shared__ float red[4][Hh];
    int b = blockIdx.x, which = blockIdx.y;
    int h = threadIdx.x & 127, kc = threadIdx.x >> 7;
    const float* w1   = which ? pw1 : cw1;
    const float* bias = which ? pb1 : cb1;
    int rowoff = which ? (Dd + KD) : Dd;
    const float* qb = q + b*Dd;
    float acc = 0.f;
    #pragma unroll 4
    for (int k = kc*96; k < kc*96 + 96; k++)
        acc = fmaf(qb[k], w1[(size_t)(rowoff + k)*Hh + h], acc);
    red[kc][h] = acc;
    __syncthreads();
    if (kc == 0)
        g_qh[(which*Bb + b)*Hh + h] = bias[h] + ((red[0][h] + red[1][h])
                                              +  (red[2][h] + red[3][h]));
}

// ---------------------------------------------------------------------------
// pre-convert fused W1 sent-block to fp16, layout [k/16][k%16][n] (n<128 coin)
// ---------------------------------------------------------------------------
__global__ void prepB_kernel(const float* __restrict__ cw1, const float* __restrict__ pw1) {
    int k = blockIdx.x;          // 0..383
    int n = threadIdx.x;         // 0..255
    const float* w = (n < Hh) ? cw1 : pw1;
    float v = w[(size_t)k*Hh + (n & (Hh-1))];
    g_Bh[(k >> 4)*(16*NB) + (k & 15)*NB + n] = __float2half_rn(v);
}

// ---------------------------------------------------------------------------
// HMMA GEMM: CTA = 128 rows x 128 cols (which = bid&1: 0 coin, 1 path),
// K=384 in 8 chunks of 48, fp16 single pass, fp32 accum.
// 3-stage smem pipeline; B via cp.async; A via coalesced flat-unit LDG
// (warp reads 512B consecutive) -> cvt -> STS.64. 8 warps = 4(M) x 2(N),
// 2 CTAs/SM.
// ---------------------------------------------------------------------------
__global__ void __launch_bounds__(256, 2)
gemm_hmma(const float* __restrict__ A,
          const float* __restrict__ cw2, const float* __restrict__ cb2) {
    extern __shared__ char smem[];
    const uint32_t sbase = smem_u32(smem);
    const int tid = threadIdx.x, lane = tid & 31, wid = tid >> 5;
    const int wm = wid >> 1, wn = wid & 1;
    const int which = blockIdx.x & 1;
    const size_t row0 = (size_t)(blockIdx.x >> 1) * 128;

    float c[2][8][4];
    #pragma unroll
    for (int i = 0; i < 2; i++)
        #pragma unroll
        for (int j = 0; j < 8; j++)
            #pragma unroll
            for (int l = 0; l < 4; l++) c[i][j][l] = 0.f;

    // A: flat-unit mapping. Chunk = 128 rows x 48 floats = 1536 x 16B units.
    // Thread t handles units t + 256*i (i=0..5): warp-consecutive -> coalesced.
    uint32_t a_goff[6];   // gmem float offset within row-block
    uint32_t a_soff[6];   // smem byte offset (fp16)
    #pragma unroll
    for (int i = 0; i < 6; i++) {
        int u = tid + 256*i;
        int r = u / 12, cc = u % 12;
        a_goff[i] = (uint32_t)r*Dd + (uint32_t)cc*4;
        a_soff[i] = (uint32_t)r*A_STRIDE + (uint32_t)cc*8;
    }
    const float* Abase = A + row0*Dd;
    // B: thread -> rows {brow, brow+16, brow+32}, 8 halves at bn8
    const int brow = tid >> 4, bn8 = (tid & 15)*8;
    const int b_src0 = brow*NB + which*Hh + bn8;
    const uint32_t b_sts0 = A_BYTES + (uint32_t)brow*B_STRIDE + (uint32_t)bn8*2;

    // ldmatrix lane offsets
    const uint32_t a_lane = (uint32_t)(lane & 15)*A_STRIDE + (uint32_t)(lane >> 4)*16;
    const uint32_t b_lane = (uint32_t)((lane & 7) + ((lane >> 3) & 1)*8)*B_STRIDE
                          + (uint32_t)(wn*64 + (lane >> 4)*8)*2;

    float4 areg[6];

    #define LDG_A(ch) do {                                                     \
        _Pragma("unroll")                                                      \
        for (int _i = 0; _i < 6; _i++)                                         \
            areg[_i] = *(const float4*)(Abase + (ch)*KC + a_goff[_i]);         \
    } while (0)

    #define STS_A(bufbyte) do {                                               \
        char* _bc = smem + (bufbyte);                                          \
        _Pragma("unroll")                                                      \
        for (int _i = 0; _i < 6; _i++) {                                       \
            uint32_t _lo = pack_h2(__float2half_rn(areg[_i].x),                \
                                   __float2half_rn(areg[_i].y));               \
            uint32_t _hi = pack_h2(__float2half_rn(areg[_i].z),                \
                                   __float2half_rn(areg[_i].w));               \
            *(uint2*)(_bc + a_soff[_i]) = make_uint2(_lo, _hi);                \
        }                                                                      \
    } while (0)

    #define CP_B(ch, bufbyte) do {                                            \
        _Pragma("unroll")                                                      \
        for (int _j = 0; _j < 3; _j++)                                         \
            cp16(sbase + (bufbyte) + b_sts0 + (uint32_t)_j*16*B_STRIDE,        \
                 g_Bh + ((ch)*3 + _j)*4096 + b_src0);                          \
        asm volatile("cp.async.commit_group;" ::: "memory");                   \
    } while (0)

    // prologue: buf0 <- chunk0, buf1 <- B(1) in flight
    LDG_A(0);
    CP_B(0, 0);
    CP_B(1, SMBUF);
    STS_A(0);
    asm volatile("cp.async.wait_group 1;" ::: "memory");
    __syncthreads();

    for (int ch = 0; ch < NCH; ch++) {
        const uint32_t bufc = (uint32_t)(ch % 3)*SMBUF;
        if (ch + 1 < NCH) LDG_A(ch + 1);
        // ---- MMA on buffer cur ----
        {
            const uint32_t sb0 = sbase + bufc;
            #pragma unroll
            for (int s = 0; s < 3; s++) {
                unsigned af[2][4];
                #pragma unroll
                for (int rg = 0; rg < 2; rg++)
                    ldsm4(af[rg][0], af[rg][1], af[rg][2], af[rg][3],
                          sb0 + (uint32_t)((wm*32 + rg*16)*A_STRIDE) + a_lane
                              + (uint32_t)s*32);
                #pragma unroll
                for (int pr = 0; pr < 4; pr++) {
                    unsigned b0, b1, b2_, b3;
                    ldsm4t(b0, b1, b2_, b3,
                           sb0 + A_BYTES + (uint32_t)s*(16*B_STRIDE)
                               + (uint32_t)pr*32 + b_lane);
                    #pragma unroll
                    for (int rg = 0; rg < 2; rg++) {
                        mma16816(c[rg][2*pr],     af[rg], b0,  b1);
                        mma16816(c[rg][2*pr + 1], af[rg], b2_, b3);
                    }
                }
            }
        }
        if (ch + 1 < NCH) STS_A((uint32_t)((ch + 1) % 3)*SMBUF);
        if (ch + 2 < NCH) {
            CP_B(ch + 2, (uint32_t)((ch + 2) % 3)*SMBUF);
            asm volatile("cp.async.wait_group 1;" ::: "memory");
        } else {
            asm volatile("cp.async.wait_group 0;" ::: "memory");
        }
        __syncthreads();
    }

    const int gr = lane >> 2, gq = lane & 3, gc2 = gq*2;

    if (which == 1) {
        // path: raw store to g_Cp
        #pragma unroll
        for (int rg = 0; rg < 2; rg++)
            #pragma unroll
            for (int ng = 0; ng < 8; ng++) {
                int r = wm*32 + rg*16 + gr;
                int pcol = wn*64 + ng*8 + gc2;
                *(float2*)&g_Cp[(row0 + r)*Hh + pcol]     = make_float2(c[rg][ng][0], c[rg][ng][1]);
                *(float2*)&g_Cp[(row0 + r + 8)*Hh + pcol] = make_float2(c[rg][ng][2], c[rg][ng][3]);
            }
        return;
    }

    // ---- coin epilogue: layer-2 via quad-shuffle partials ----
    const int b = blockIdx.x >> 7;            // 64 tiles * 2 per batch
    float* part = (float*)smem;               // [128][2][8]
    float* w2s  = (float*)(smem + 8192);      // [128*8]
    float* qhs  = (float*)(smem + 12288);     // [128]
    float* b2s  = (float*)(smem + 12800);     // [8]
    for (int i = tid; i < Hh*KD; i += 256) w2s[i] = cw2[i];
    if (tid < Hh) qhs[tid] = g_qh[b*Hh + tid];
    if (tid < KD) b2s[tid] = cb2[tid];
    __syncthreads();

    #pragma unroll
    for (int rg = 0; rg < 2; rg++) {
        float pa[8], pb[8];
        #pragma unroll
        for (int j = 0; j < 8; j++) { pa[j] = 0.f; pb[j] = 0.f; }
        #pragma unroll
        for (int ng = 0; ng < 8; ng++) {
            int col = wn*64 + ng*8 + gc2;
            float qa = qhs[col], qb = qhs[col + 1];
            float h0 = fmaxf(c[rg][ng][0] + qa, 0.f);
            float h1 = fmaxf(c[rg][ng][1] + qb, 0.f);
            float h2 = fmaxf(c[rg][ng][2] + qa, 0.f);
            float h3 = fmaxf(c[rg][ng][3] + qb, 0.f);
            #pragma unroll
            for (int j = 0; j < 8; j++) {
                float w0 = w2s[col*8 + j], w1 = w2s[(col + 1)*8 + j];
                pa[j] += h0*w0 + h1*w1;
                pb[j] += h2*w0 + h3*w1;
            }
        }
        #pragma unroll
        for (int j = 0; j < 8; j++) {
            pa[j] += __shfl_xor_sync(0xffffffffu, pa[j], 1);
            pa[j] += __shfl_xor_sync(0xffffffffu, pa[j], 2);
            pb[j] += __shfl_xor_sync(0xffffffffu, pb[j], 1);
            pb[j] += __shfl_xor_sync(0xffffffffu, pb[j], 2);
        }
        if (gq == 0) {
            int row = wm*32 + rg*16 + gr;
            #pragma unroll
            for (int j = 0; j < 8; j++) {
                part[(row*2 + wn)*8 + j]       = pa[j];
                part[((row + 8)*2 + wn)*8 + j] = pb[j];
            }
        }
    }
    __syncthreads();

    #pragma unroll
    for (int it = 0; it < 4; it++) {
        int idx = it*256 + tid;
        int row = idx >> 3, j = idx & 7;
        float acc = b2s[j] + part[(row*2)*8 + j] + part[(row*2 + 1)*8 + j];
        g_amps[(row0 + row)*KD + j] = acc;
        g_t[0][(row0 + row)*KD + j] = acc * 0.00390625f;
    }
}

// ---------------------------------------------------------------------------
// One walk step. Warp-level coef (no barriers); 2 barriers total.
// ---------------------------------------------------------------------------
__global__ void walk_kernel(const int* __restrict__ nbrs, int step) {
    __shared__ int   nb[128*KN];
    __shared__ float red[8];
    int b  = blockIdx.y;
    int n0 = blockIdx.x * 128;
    int tid = threadIdx.x, lane = tid & 31, wid = tid >> 5;

    const int4* nb_g = (const int4*)(nbrs + ((size_t)(b*Nn + n0))*KN);
    int4* nb4 = (int4*)nb;
    nb4[tid]       = nb_g[tid];
    nb4[tid + 256] = nb_g[tid + 256];

    float coef = 1.0f;
    if (step > 0) {
        float p = g_part[b*64 + lane] + g_part[b*64 + 32 + lane];
        #pragma unroll
        for (int m = 16; m > 0; m >>= 1) p += __shfl_xor_sync(0xffffffffu, p, m);
        coef = (p > 0.f) ? rsqrtf(p) : 1.0f;
    }
    __syncthreads();

    int node = tid >> 1, kh = (tid & 1)*4;
    int n = n0 + node;
    const float* tb = g_t[step & 1] + (size_t)b*Nn*KD;

    float4 acc = *(const float4*)(tb + n*KD + kh);
    #pragma unroll
    for (int j = 0; j < KN; j++) {
        int idx = nb[node*KN + j];
        if (idx >= 0 && idx < Nn) {
            float4 v = *(const float4*)(tb + idx*KD + kh);
            acc.x += v.x; acc.y += v.y; acc.z += v.z; acc.w += v.w;
        }
    }
    float4 ns = make_float4(coef*acc.x, coef*acc.y, coef*acc.z, coef*acc.w);

    size_t gi = ((size_t)b*Nn + n)*KD + kh;
    if (step < STEPS - 1) {
        float4 am = *(const float4*)(g_amps + gi);
        *(float4*)(g_t[(step + 1) & 1] + gi) =
            make_float4(ns.x*am.x, ns.y*am.y, ns.z*am.z, ns.w*am.w);
    } else {
        *(float4*)(g_nsL + gi) = ns;
    }

    float s = ns.x*ns.x + ns.y*ns.y + ns.z*ns.z + ns.w*ns.w;
    #pragma unroll
    for (int m = 16; m > 0; m >>= 1) s += __shfl_xor_sync(0xffffffffu, s, m);
    if (lane == 0) red[wid] = s;
    __syncthreads();
    if (tid == 0) {
        float t = 0.f;
        #pragma unroll
        for (int i = 0; i < 8; i++) t += red[i];
        g_part[b*64 + blockIdx.x] = t;
    }
}

// ---------------------------------------------------------------------------
// Final path MLP. Warp-level coef (no block reduce barriers).
// ---------------------------------------------------------------------------
__global__ void final_kernel(const float* __restrict__ pw1,
                             const float* __restrict__ w2, const float* __restrict__ b2,
                             float* __restrict__ out) {
    __shared__ float wst[KD*Hh];
    __shared__ float w2s[Hh];
    int tid = threadIdx.x, lane = tid & 31;
    int b = blockIdx.x >> 10;   // 1024 blocks per batch

    for (int i = tid; i < KD*Hh; i += 256) wst[i] = pw1[(size_t)Dd*Hh + i];
    if (tid < Hh) w2s[tid] = w2[tid];

    float p = g_part[b*64 + lane] + g_part[b*64 + 32 + lane];
    #pragma unroll
    for (int m = 16; m > 0; m >>= 1) p += __shfl_xor_sync(0xffffffffu, p, m);
    float inv = (p > 0.f) ? rsqrtf(p) : 1.0f;
    __syncthreads();

    int r = blockIdx.x*8 + (tid >> 5);
    int l = lane;

    const float* nsf = g_nsL + (size_t)r*KD;
    float s[KD];
    #pragma unroll
    for (int k = 0; k < KD; k++) s[k] = nsf[k] * inv;

    float4 cc = *(const float4*)&g_Cp[(size_t)r*Hh + l*4];
    float4 qv = *(const float4*)&g_qh[(Bb + b)*Hh + l*4];
    float hv[4] = { cc.x+qv.x, cc.y+qv.y, cc.z+qv.z, cc.w+qv.w };
    #pragma unroll
    for (int k = 0; k < KD; k++)
        #pragma unroll
        for (int i = 0; i < 4; i++)
            hv[i] = fmaf(s[k], wst[k*Hh + l*4 + i], hv[i]);

    float part = 0.f;
    #pragma unroll
    for (int i = 0; i < 4; i++) {
        float h = fmaxf(hv[i], 0.f);
        part = fmaf(h, w2s[l*4 + i], part);
    }
    #pragma unroll
    for (int m = 16; m > 0; m >>= 1)
        part += __shfl_xor_sync(0xffffffffu, part, m);
    if (l == 0) out[r] = part + b2[0];
}

// ---------------------------------------------------------------------------
extern "C" void kernel_launch(void* const* d_in, const int* in_sizes, int n_in,
                              void* d_out, int out_size) {
    const float* sent = (const float*)d_in[0];
    const float* q    = (const float*)d_in[1];
    const int*   nbrs = (const int*)  d_in[2];
    const float* cw1  = (const float*)d_in[3];
    const float* cb1  = (const float*)d_in[4];
    const float* cw2  = (const float*)d_in[5];
    const float* cb2  = (const float*)d_in[6];
    const float* pw1  = (const float*)d_in[7];
    const float* pb1  = (const float*)d_in[8];
    const float* pw2  = (const float*)d_in[9];
    const float* pb2  = (const float*)d_in[10];
    float* out = (float*)d_out;

    cudaFuncSetAttribute(gemm_hmma, cudaFuncAttributeMaxDynamicSharedMemorySize, SM_TOTAL);

    qh_kernel<<<dim3(Bb, 2), 512>>>(q, cw1, cb1, pw1, pb1);
    prepB_kernel<<<Dd, NB>>>(cw1, pw1);
    gemm_hmma<<<(M_TOT/128)*2, 256, SM_TOTAL>>>(sent, cw2, cb2);
    for (int s = 0; s < STEPS; s++)
        walk_kernel<<<dim3(Nn/128, Bb), 256>>>(nbrs, s);
    final_kernel<<<M_TOT/8, 256>>>(pw1, pw2, pb2, out);
}